// round 3
// baseline (speedup 1.0000x reference)
#include <cuda_runtime.h>

#define N_USERS 100000
#define N_ITEMS 50000
#define NTOT    150000        // N_USERS + N_ITEMS (same for both graphs)
#define D       64
#define BATCH   4096
#define NLAYERS 3

// -------- static scratch (no allocation allowed) --------
__device__ float g_bufA[(size_t)NTOT * D];
__device__ float g_bufB[(size_t)NTOT * D];
__device__ float g_acc1[(size_t)NTOT * D];
__device__ float g_acc2[(size_t)NTOT * D];
__device__ int   g_rowptr1[NTOT + 1];
__device__ int   g_rowptr2[NTOT + 1];

__device__ __forceinline__ float* sel(int w) {
    switch (w) {
        case 0:  return g_bufA;
        case 1:  return g_bufB;
        case 2:  return g_acc1;
        default: return g_acc2;
    }
}

// rows[] is sorted; rowptr[r] = lower_bound(rows, r)
__global__ void build_rowptr_kernel(const int* __restrict__ rows, int nnz, int which) {
    int r = blockIdx.x * blockDim.x + threadIdx.x;
    if (r > NTOT) return;
    int lo = 0, hi = nnz;
    while (lo < hi) {
        int mid = (lo + hi) >> 1;
        if (__ldg(rows + mid) < r) lo = mid + 1; else hi = mid;
    }
    (which == 0 ? g_rowptr1 : g_rowptr2)[r] = lo;
}

// concat(user_emb, item_emb) -> cur buffer, and initialize accumulator = e0
__global__ void pack_kernel(const float* __restrict__ ue, const float* __restrict__ ie,
                            int cur_sel, int acc_sel) {
    size_t i = (size_t)blockIdx.x * blockDim.x + threadIdx.x;   // float4 index
    const size_t total = (size_t)NTOT * D / 4;
    if (i >= total) return;
    const size_t nu = (size_t)N_USERS * D / 4;
    float4 v = (i < nu) ? ((const float4*)ue)[i] : ((const float4*)ie)[i - nu];
    float* cur = sel(cur_sel);
    float* acc = sel(acc_sel);
    ((float4*)cur)[i] = v;
    ((float4*)acc)[i] = v;
}

// warp-per-row CSR SpMM: out[r,:] = sum_j vals[j] * in[cols[j],:]; acc += out
// store_out==0 on the last layer: the ping-pong output is dead there.
__global__ void __launch_bounds__(256)
spmm_kernel(const int* __restrict__ cols, const float* __restrict__ vals,
            int in_sel, int out_sel, int acc_sel, int which, int store_out) {
    int gw   = (int)((blockIdx.x * blockDim.x + threadIdx.x) >> 5);
    int lane = threadIdx.x & 31;
    if (gw >= NTOT) return;

    const float* __restrict__ in  = sel(in_sel);
    float*       __restrict__ out = sel(out_sel);
    float*       __restrict__ acc = sel(acc_sel);
    const int*   __restrict__ rp  = (which == 0) ? g_rowptr1 : g_rowptr2;

    int s = rp[gw];
    int e = rp[gw + 1];

    float ax = 0.f, ay = 0.f;
    int j = s;
    // 8-deep unroll: independent col/val/emb loads -> MLP ~8 on the L2 gather chain
    for (; j + 8 <= e; j += 8) {
        int   c[8]; float v[8]; float2 ev[8];
        #pragma unroll
        for (int k = 0; k < 8; ++k) c[k] = __ldg(cols + j + k);
        #pragma unroll
        for (int k = 0; k < 8; ++k) v[k] = __ldg(vals + j + k);
        #pragma unroll
        for (int k = 0; k < 8; ++k)
            ev[k] = *(const float2*)(in + (size_t)c[k] * D + lane * 2);
        #pragma unroll
        for (int k = 0; k < 8; ++k) {
            ax = fmaf(v[k], ev[k].x, ax);
            ay = fmaf(v[k], ev[k].y, ay);
        }
    }
    for (; j < e; ++j) {
        int   c = __ldg(cols + j);
        float v = __ldg(vals + j);
        float2 evs = *(const float2*)(in + (size_t)c * D + lane * 2);
        ax = fmaf(v, evs.x, ax); ay = fmaf(v, evs.y, ay);
    }

    size_t o = (size_t)gw * D + lane * 2;
    if (store_out)
        *(float2*)(out + o) = make_float2(ax, ay);
    float2 av = *(float2*)(acc + o);
    av.x += ax; av.y += ay;
    *(float2*)(acc + o) = av;
}

// final: out[seg, b, :] = acc_table[idx, :] / 4  for the 6 index sets
__global__ void gather_kernel(const int* __restrict__ u1, const int* __restrict__ p1,
                              const int* __restrict__ n1, const int* __restrict__ u2,
                              const int* __restrict__ p2, const int* __restrict__ n2,
                              float* __restrict__ out) {
    int gw   = (int)((blockIdx.x * blockDim.x + threadIdx.x) >> 5);
    int lane = threadIdx.x & 31;
    if (gw >= 6 * BATCH) return;
    int seg = gw / BATCH;
    int b   = gw - seg * BATCH;

    const float* table;
    int idx;
    switch (seg) {
        case 0:  table = g_acc1; idx = __ldg(u1 + b);           break;
        case 1:  table = g_acc1; idx = N_USERS + __ldg(p1 + b); break;
        case 2:  table = g_acc1; idx = N_USERS + __ldg(n1 + b); break;
        case 3:  table = g_acc2; idx = __ldg(u2 + b);           break;
        case 4:  table = g_acc2; idx = N_USERS + __ldg(p2 + b); break;
        default: table = g_acc2; idx = N_USERS + __ldg(n2 + b); break;
    }
    float2 v = *(const float2*)(table + (size_t)idx * D + lane * 2);
    *(float2*)(out + (size_t)gw * D + lane * 2) = make_float2(v.x * 0.25f, v.y * 0.25f);
}

extern "C" void kernel_launch(void* const* d_in, const int* in_sizes, int n_in,
                              void* d_out, int out_size) {
    const int*   rows1 = (const int*)  d_in[0];
    const int*   cols1 = (const int*)  d_in[1];
    const float* vals1 = (const float*)d_in[2];
    const int*   rows2 = (const int*)  d_in[3];
    const int*   cols2 = (const int*)  d_in[4];
    const float* vals2 = (const float*)d_in[5];
    const float* ue1   = (const float*)d_in[6];
    const float* ie1   = (const float*)d_in[7];
    const float* ue2   = (const float*)d_in[8];
    const float* ie2   = (const float*)d_in[9];
    const int*   u1    = (const int*)  d_in[10];
    const int*   p1    = (const int*)  d_in[11];
    const int*   n1    = (const int*)  d_in[12];
    const int*   u2    = (const int*)  d_in[13];
    const int*   p2    = (const int*)  d_in[14];
    const int*   n2    = (const int*)  d_in[15];
    float* out = (float*)d_out;

    const int nnz1 = in_sizes[0];
    const int nnz2 = in_sizes[3];
    const int TPB = 256;
    const int rowptr_blocks = (NTOT + 1 + TPB - 1) / TPB;
    const int pack_blocks   = (int)(((size_t)NTOT * D / 4 + TPB - 1) / TPB);
    const int spmm_blocks   = (int)(((size_t)NTOT * 32 + TPB - 1) / TPB);

    // ---- graph 1 (accumulate into g_acc1 = buf sel 2) ----
    build_rowptr_kernel<<<rowptr_blocks, TPB>>>(rows1, nnz1, 0);
    pack_kernel<<<pack_blocks, TPB>>>(ue1, ie1, /*cur=*/0, /*acc=*/2);
    int cur = 0, nxt = 1;
    for (int l = 0; l < NLAYERS; ++l) {
        spmm_kernel<<<spmm_blocks, TPB>>>(cols1, vals1, cur, nxt, /*acc=*/2, 0,
                                          l < NLAYERS - 1 ? 1 : 0);
        int t = cur; cur = nxt; nxt = t;
    }

    // ---- graph 2 (accumulate into g_acc2 = buf sel 3) ----
    build_rowptr_kernel<<<rowptr_blocks, TPB>>>(rows2, nnz2, 1);
    pack_kernel<<<pack_blocks, TPB>>>(ue2, ie2, /*cur=*/0, /*acc=*/3);
    cur = 0; nxt = 1;
    for (int l = 0; l < NLAYERS; ++l) {
        spmm_kernel<<<spmm_blocks, TPB>>>(cols2, vals2, cur, nxt, /*acc=*/3, 1,
                                          l < NLAYERS - 1 ? 1 : 0);
        int t = cur; cur = nxt; nxt = t;
    }

    // ---- batched gathers: out[6, BATCH, D] = light_out[idx]/4 ----
    const int gather_blocks = (6 * BATCH * 32 + TPB - 1) / TPB;
    gather_kernel<<<gather_blocks, TPB>>>(u1, p1, n1, u2, p2, n2, out);
}

// round 4
// speedup vs baseline: 1.0662x; 1.0662x over previous
#include <cuda_runtime.h>

#define N_USERS 100000
#define N_ITEMS 50000
#define NTOT    150000
#define D       64
#define BATCH   4096
#define NLAYERS 3

// -------- static scratch: e0..e3 per graph (no accumulator needed) --------
__device__ float g_e0a[(size_t)NTOT * D];
__device__ float g_e1a[(size_t)NTOT * D];
__device__ float g_e2a[(size_t)NTOT * D];
__device__ float g_e3a[(size_t)NTOT * D];
__device__ float g_e0b[(size_t)NTOT * D];
__device__ float g_e1b[(size_t)NTOT * D];
__device__ float g_e2b[(size_t)NTOT * D];
__device__ float g_e3b[(size_t)NTOT * D];
__device__ int   g_rowptr1[NTOT + 1];
__device__ int   g_rowptr2[NTOT + 1];

__device__ __forceinline__ float* sel(int w) {
    switch (w) {
        case 0:  return g_e0a;
        case 1:  return g_e1a;
        case 2:  return g_e2a;
        case 3:  return g_e3a;
        case 4:  return g_e0b;
        case 5:  return g_e1b;
        case 6:  return g_e2b;
        default: return g_e3b;
    }
}

// rows[] is sorted; rowptr[r] = lower_bound(rows, r)
__global__ void build_rowptr_kernel(const int* __restrict__ rows, int nnz, int which) {
    int r = blockIdx.x * blockDim.x + threadIdx.x;
    if (r > NTOT) return;
    int lo = 0, hi = nnz;
    while (lo < hi) {
        int mid = (lo + hi) >> 1;
        if (__ldg(rows + mid) < r) lo = mid + 1; else hi = mid;
    }
    (which == 0 ? g_rowptr1 : g_rowptr2)[r] = lo;
}

// concat(user_emb, item_emb) -> e0 buffer
__global__ void pack_kernel(const float* __restrict__ ue, const float* __restrict__ ie,
                            int dst_sel) {
    size_t i = (size_t)blockIdx.x * blockDim.x + threadIdx.x;   // float4 index
    const size_t total = (size_t)NTOT * D / 4;
    if (i >= total) return;
    const size_t nu = (size_t)N_USERS * D / 4;
    float4 v = (i < nu) ? ((const float4*)ue)[i] : ((const float4*)ie)[i - nu];
    ((float4*)sel(dst_sel))[i] = v;
}

// warp-per-row CSR SpMM: out[r,:] = sum_j vals[j] * in[cols[j],:]
// Full 8-wide batching: indices clamped, vals zeroed past end -> MLP 8 on every edge.
__global__ void __launch_bounds__(256)
spmm_kernel(const int* __restrict__ cols, const float* __restrict__ vals,
            int in_sel, int out_sel, int which) {
    int gw   = (int)((blockIdx.x * blockDim.x + threadIdx.x) >> 5);
    int lane = threadIdx.x & 31;
    if (gw >= NTOT) return;

    const float* __restrict__ in  = sel(in_sel);
    float*       __restrict__ out = sel(out_sel);
    const int*   __restrict__ rp  = (which == 0) ? g_rowptr1 : g_rowptr2;

    int s = rp[gw];
    int e = rp[gw + 1];

    float ax = 0.f, ay = 0.f;
    if (e > s) {
        int last = e - 1;
        for (int j = s; j < e; j += 8) {
            int   c[8]; float v[8]; float2 ev[8];
            #pragma unroll
            for (int k = 0; k < 8; ++k) {
                int jj = j + k;
                int ji = jj <= last ? jj : last;       // clamp (duplicate last, val=0)
                c[k] = __ldg(cols + ji);
            }
            #pragma unroll
            for (int k = 0; k < 8; ++k) {
                int jj = j + k;
                v[k] = (jj <= last) ? __ldg(vals + jj) : 0.f;
            }
            #pragma unroll
            for (int k = 0; k < 8; ++k)
                ev[k] = *(const float2*)(in + (size_t)c[k] * D + lane * 2);
            #pragma unroll
            for (int k = 0; k < 8; ++k) {
                ax = fmaf(v[k], ev[k].x, ax);
                ay = fmaf(v[k], ev[k].y, ay);
            }
        }
    }

    size_t o = (size_t)gw * D + lane * 2;
    *(float2*)(out + o) = make_float2(ax, ay);
}

// final: out[seg, b, :] = mean(e0..e3)[idx, :]  for the 6 index sets
__global__ void gather_kernel(const int* __restrict__ u1, const int* __restrict__ p1,
                              const int* __restrict__ n1, const int* __restrict__ u2,
                              const int* __restrict__ p2, const int* __restrict__ n2,
                              float* __restrict__ out) {
    int gw   = (int)((blockIdx.x * blockDim.x + threadIdx.x) >> 5);
    int lane = threadIdx.x & 31;
    if (gw >= 6 * BATCH) return;
    int seg = gw / BATCH;
    int b   = gw - seg * BATCH;

    int idx; int g2;
    switch (seg) {
        case 0:  idx = __ldg(u1 + b);           g2 = 0; break;
        case 1:  idx = N_USERS + __ldg(p1 + b); g2 = 0; break;
        case 2:  idx = N_USERS + __ldg(n1 + b); g2 = 0; break;
        case 3:  idx = __ldg(u2 + b);           g2 = 1; break;
        case 4:  idx = N_USERS + __ldg(p2 + b); g2 = 1; break;
        default: idx = N_USERS + __ldg(n2 + b); g2 = 1; break;
    }
    size_t o = (size_t)idx * D + lane * 2;
    const float* t0 = g2 ? g_e0b : g_e0a;
    const float* t1 = g2 ? g_e1b : g_e1a;
    const float* t2 = g2 ? g_e2b : g_e2a;
    const float* t3 = g2 ? g_e3b : g_e3a;
    float2 v0 = *(const float2*)(t0 + o);
    float2 v1 = *(const float2*)(t1 + o);
    float2 v2 = *(const float2*)(t2 + o);
    float2 v3 = *(const float2*)(t3 + o);
    float2 r;
    r.x = (v0.x + v1.x + v2.x + v3.x) * 0.25f;
    r.y = (v0.y + v1.y + v2.y + v3.y) * 0.25f;
    *(float2*)(out + (size_t)gw * D + lane * 2) = r;
}

extern "C" void kernel_launch(void* const* d_in, const int* in_sizes, int n_in,
                              void* d_out, int out_size) {
    const int*   rows1 = (const int*)  d_in[0];
    const int*   cols1 = (const int*)  d_in[1];
    const float* vals1 = (const float*)d_in[2];
    const int*   rows2 = (const int*)  d_in[3];
    const int*   cols2 = (const int*)  d_in[4];
    const float* vals2 = (const float*)d_in[5];
    const float* ue1   = (const float*)d_in[6];
    const float* ie1   = (const float*)d_in[7];
    const float* ue2   = (const float*)d_in[8];
    const float* ie2   = (const float*)d_in[9];
    const int*   u1    = (const int*)  d_in[10];
    const int*   p1    = (const int*)  d_in[11];
    const int*   n1    = (const int*)  d_in[12];
    const int*   u2    = (const int*)  d_in[13];
    const int*   p2    = (const int*)  d_in[14];
    const int*   n2    = (const int*)  d_in[15];
    float* out = (float*)d_out;

    const int nnz1 = in_sizes[0];
    const int nnz2 = in_sizes[3];
    const int TPB = 256;
    const int rowptr_blocks = (NTOT + 1 + TPB - 1) / TPB;
    const int pack_blocks   = (int)(((size_t)NTOT * D / 4 + TPB - 1) / TPB);
    const int spmm_blocks   = (int)(((size_t)NTOT * 32 + TPB - 1) / TPB);

    // ---- graph 1: e0a -> e1a -> e2a -> e3a ----
    build_rowptr_kernel<<<rowptr_blocks, TPB>>>(rows1, nnz1, 0);
    pack_kernel<<<pack_blocks, TPB>>>(ue1, ie1, 0);
    for (int l = 0; l < NLAYERS; ++l)
        spmm_kernel<<<spmm_blocks, TPB>>>(cols1, vals1, l, l + 1, 0);

    // ---- graph 2: e0b -> e1b -> e2b -> e3b ----
    build_rowptr_kernel<<<rowptr_blocks, TPB>>>(rows2, nnz2, 1);
    pack_kernel<<<pack_blocks, TPB>>>(ue2, ie2, 4);
    for (int l = 0; l < NLAYERS; ++l)
        spmm_kernel<<<spmm_blocks, TPB>>>(cols2, vals2, 4 + l, 4 + l + 1, 1);

    // ---- batched gathers with on-the-fly layer mean ----
    const int gather_blocks = (6 * BATCH * 32 + TPB - 1) / TPB;
    gather_kernel<<<gather_blocks, TPB>>>(u1, p1, n1, u2, p2, n2, out);
}